// round 7
// baseline (speedup 1.0000x reference)
#include <cuda_runtime.h>
#include <cuda_bf16.h>
#include <math.h>
#include <stdint.h>

// ---------------- scratch (device globals) ---------------------------------------
__device__ __nv_bfloat16 g_hh[26214400];   // conv1 out hi, [b][pos400][ci256]
__device__ __nv_bfloat16 g_hl[26214400];   // conv1 out lo
__device__ __nv_bfloat16 g_whi[5308416];   // prim weights hi, [tap81][co256][ci256]
__device__ __nv_bfloat16 g_wlo[5308416];
__device__ float g_x3[256 * 1152 * 8];     // squashed primary caps [b][i][a]
__device__ float g_votes[47185920];        // votes [i][b][ot]
__device__ float g_r1[256 * 512];
__device__ float g_r2[256 * 1024];

// ---------------- f32x2 helpers ---------------------------------------------------
__device__ __forceinline__ unsigned long long pk2(float lo, float hi) {
    unsigned long long r;
    asm("mov.b64 %0, {%1, %2};" : "=l"(r) : "f"(lo), "f"(hi));
    return r;
}
__device__ __forceinline__ void fma2(unsigned long long& d, unsigned long long a,
                                     unsigned long long b) {
    asm("fma.rn.f32x2 %0, %1, %2, %0;" : "+l"(d) : "l"(a), "l"(b));
}
__device__ __forceinline__ float2 upk2(unsigned long long v) {
    float2 f;
    asm("mov.b64 {%0, %1}, %2;" : "=f"(f.x), "=f"(f.y) : "l"(v));
    return f;
}

// ---------------- baseline-PTX helpers (NO sm_103a-gated instructions) ------------
__device__ __forceinline__ uint32_t smem_to_u32(const void* p) {
    uint32_t a;
    asm("{ .reg .u64 t; cvta.to.shared.u64 t, %1; cvt.u32.u64 %0, t; }" : "=r"(a) : "l"(p));
    return a;
}
__device__ __forceinline__ void cpa16(uint32_t s, const void* g) {
    asm volatile("cp.async.cg.shared.global [%0], [%1], 16;" :: "r"(s), "l"(g));
}
#define CP_COMMIT() asm volatile("cp.async.commit_group;" ::: "memory")
#define CP_WAIT0()  asm volatile("cp.async.wait_group 0;" ::: "memory")

__device__ __forceinline__ void ldm_x4(uint32_t& r0, uint32_t& r1, uint32_t& r2,
                                       uint32_t& r3, uint32_t a) {
    asm volatile("ldmatrix.sync.aligned.m8n8.x4.shared.b16 {%0,%1,%2,%3}, [%4];"
                 : "=r"(r0), "=r"(r1), "=r"(r2), "=r"(r3) : "r"(a));
}
__device__ __forceinline__ void ldm_x2(uint32_t& r0, uint32_t& r1, uint32_t a) {
    asm volatile("ldmatrix.sync.aligned.m8n8.x2.shared.b16 {%0,%1}, [%2];"
                 : "=r"(r0), "=r"(r1) : "r"(a));
}
__device__ __forceinline__ void mma_bf16(float* c, const uint32_t* a, const uint32_t* b) {
    asm volatile("mma.sync.aligned.m16n8k16.row.col.f32.bf16.bf16.f32 "
                 "{%0,%1,%2,%3}, {%4,%5,%6,%7}, {%8,%9}, {%0,%1,%2,%3};"
                 : "+f"(c[0]), "+f"(c[1]), "+f"(c[2]), "+f"(c[3])
                 : "r"(a[0]), "r"(a[1]), "r"(a[2]), "r"(a[3]), "r"(b[0]), "r"(b[1]));
}
#define SWZ(x) ((x) ^ (((x) >> 3) & 0x70))

// ---------------- P0: weight split/transpose  [co][ci][tap] -> [tap][co][ci] ------
__global__ __launch_bounds__(512) void k_wsplit(const float* __restrict__ pw) {
    int e = blockIdx.x * 512 + threadIdx.x;   // 81*256*256 = 5,308,416 exact
    int tap = e >> 16, r = e & 65535, co = r >> 8, ci = r & 255;
    float w = pw[co * 20736 + ci * 81 + tap];
    __nv_bfloat16 hi = __float2bfloat16(w);
    g_whi[e] = hi;
    g_wlo[e] = __float2bfloat16(w - __bfloat162float(hi));
}

// ---------------- K1: conv1 9x9 s1 + bias + relu -> bf16 hi/lo [b][pos][ci] -------
__global__ __launch_bounds__(400) void k_conv1(const float* __restrict__ x,
                                               const float* __restrict__ w,
                                               const float* __restrict__ bias) {
    int b = blockIdx.y, c0 = blockIdx.x * 32;
    __shared__ float img[784];
    __shared__ float ws[32 * 81];
    __shared__ float bs[32];
    __shared__ unsigned spk[100 * 32];
    int t = threadIdx.x;
    for (int e = t; e < 784; e += 400) img[e] = x[b * 784 + e];
    for (int e = t; e < 2592; e += 400) ws[e] = w[c0 * 81 + e];
    if (t < 32) bs[t] = bias[c0 + t];
    __syncthreads();

    int pg = t % 100, chg = t / 100;
    int p0 = pg * 4;
    int oy = p0 / 20, ox0 = p0 % 20;

    unsigned long long acc2[4][4];
#pragma unroll
    for (int p = 0; p < 4; p++)
#pragma unroll
        for (int j = 0; j < 4; j++) acc2[p][j] = 0ull;

    for (int kh = 0; kh < 9; kh++) {
        const float* row = img + (oy + kh) * 28 + ox0;
        float xw[12];
#pragma unroll
        for (int i = 0; i < 12; i++) xw[i] = row[i];
#pragma unroll
        for (int kw = 0; kw < 9; kw++) {
            unsigned long long xp[4];
#pragma unroll
            for (int j = 0; j < 4; j++) xp[j] = pk2(xw[kw + j], xw[kw + j]);
#pragma unroll
            for (int p = 0; p < 4; p++) {
                unsigned long long wp = pk2(ws[(chg * 8 + 2 * p) * 81 + kh * 9 + kw],
                                            ws[(chg * 8 + 2 * p + 1) * 81 + kh * 9 + kw]);
#pragma unroll
                for (int j = 0; j < 4; j++) fma2(acc2[p][j], xp[j], wp);
            }
        }
    }

    unsigned pkv[8][4];
#pragma unroll
    for (int p = 0; p < 4; p++) {
        float b0v = bs[chg * 8 + 2 * p], b1v = bs[chg * 8 + 2 * p + 1];
#pragma unroll
        for (int j = 0; j < 4; j++) {
            float2 f = upk2(acc2[p][j]);
            float v0 = fmaxf(f.x + b0v, 0.f), v1 = fmaxf(f.y + b1v, 0.f);
            __nv_bfloat16 h0 = __float2bfloat16(v0);
            __nv_bfloat16 l0 = __float2bfloat16(v0 - __bfloat162float(h0));
            __nv_bfloat16 h1 = __float2bfloat16(v1);
            __nv_bfloat16 l1 = __float2bfloat16(v1 - __bfloat162float(h1));
            pkv[2 * p][j] = (unsigned)__bfloat16_as_ushort(h0) |
                            ((unsigned)__bfloat16_as_ushort(l0) << 16);
            pkv[2 * p + 1][j] = (unsigned)__bfloat16_as_ushort(h1) |
                                ((unsigned)__bfloat16_as_ushort(l1) << 16);
        }
    }
    for (int c = 0; c < 4; c++) {
        if (pg >= c * 25 && pg < c * 25 + 25) {
            int pl = p0 - c * 100;
#pragma unroll
            for (int ch = 0; ch < 8; ch++)
#pragma unroll
                for (int j = 0; j < 4; j++)
                    spk[(pl + j) * 32 + chg * 8 + ch] = pkv[ch][j];
        }
        __syncthreads();
        for (int e = t; e < 3200; e += 400) {
            int pl = e >> 5, ch = e & 31;
            unsigned v = spk[e];
            int gi = (b * 400 + c * 100 + pl) * 256 + c0 + ch;
            g_hh[gi] = __ushort_as_bfloat16((unsigned short)(v & 0xffff));
            g_hl[gi] = __ushort_as_bfloat16((unsigned short)(v >> 16));
        }
        __syncthreads();
    }
}

// ---------------- K2: primary-caps conv via mma.sync bf16, 3-term split ------------
// grid (2 co-halves of 128, 64 b-groups of 4), 512 thr = 16 warps (8M x 2N).
// CTA tile: M=128 co, N=144 (4b x 36 pos), K = 81 taps x 4 ci-blocks(64) = 324 stages.
// Warp tile 16x72 -> 4 warps/SMSP hide LDSM/cp.async latencies behind HMMA issue.
static constexpr int PRIM_NS = 324;

__global__ __launch_bounds__(512, 1) void k_prim(const float* __restrict__ pb) {
    extern __shared__ char sm[];
    uint32_t sb = smem_to_u32(sm);
    const int t = threadIdx.x, wid = t >> 5, lane = t & 31;
    const int co0 = blockIdx.x * 128;
    const int b0 = blockIdx.y * 4;
    const int warpM = wid >> 1, warpN = wid & 1;   // 8 x 2

    // smem regions (each 1024-aligned): Ah,Al 16KB; Bh,Bl 18KB; x2 buffers.
    const uint32_t AH[2] = {0u, 69632u};
    const uint32_t AL[2] = {16384u, 86016u};
    const uint32_t BH[2] = {32768u, 102400u};
    const uint32_t BL[2] = {51200u, 120832u};

    // staging address precompute (512 threads)
    uint32_t a_sm[2]; long a_g[2];
#pragma unroll
    for (int k = 0; k < 2; k++) {
        int e = t + k * 512, row = e >> 3, q = e & 7;
        a_sm[k] = SWZ((uint32_t)(row * 128 + q * 16));
        a_g[k] = (long)(co0 + row) * 256 + q * 8;
    }
    uint32_t b_sm[3]; long b_g[3]; bool b_p[3];
#pragma unroll
    for (int k = 0; k < 3; k++) {
        int e = t + k * 512;
        b_p[k] = (e < 1152);
        int n = e >> 3, q = e & 7;
        if (!b_p[k]) { n = 0; q = 0; }
        int bb = n / 36, sp = n % 36, oy = sp / 6, ox = sp % 6;
        b_sm[k] = SWZ((uint32_t)(n * 128 + q * 16));
        b_g[k] = (long)((b0 + bb) * 400 + oy * 40 + ox * 2) * 256 + q * 8;
    }

    auto stage = [&](int buf, int s) {
        int tap = s >> 2, cb = s & 3;
        long wofs = (long)tap * 65536 + cb * 64;
        long xofs = (long)((tap / 9) * 20 + (tap % 9)) * 256 + cb * 64;
#pragma unroll
        for (int k = 0; k < 2; k++) {
            cpa16(sb + AH[buf] + a_sm[k], g_whi + wofs + a_g[k]);
            cpa16(sb + AL[buf] + a_sm[k], g_wlo + wofs + a_g[k]);
        }
#pragma unroll
        for (int k = 0; k < 3; k++) {
            if (b_p[k]) {
                cpa16(sb + BH[buf] + b_sm[k], g_hh + xofs + b_g[k]);
                cpa16(sb + BL[buf] + b_sm[k], g_hl + xofs + b_g[k]);
            }
        }
        CP_COMMIT();
    };

    float acc[9][4];
#pragma unroll
    for (int nt = 0; nt < 9; nt++)
#pragma unroll
        for (int j = 0; j < 4; j++) acc[nt][j] = 0.f;

    const int arow = warpM * 16 + (lane & 15);
    const int n0w = warpN * 72;
    const int csel = (lane >> 4) * 16;

    stage(0, 0);
    CP_WAIT0();
    __syncthreads();

    for (int s = 0; s < PRIM_NS; s++) {
        int cur = s & 1;
        if (s + 1 < PRIM_NS) stage(cur ^ 1, s + 1);

        uint32_t bA_h = sb + AH[cur], bA_l = sb + AL[cur];
        uint32_t bB_h = sb + BH[cur], bB_l = sb + BL[cur];
#pragma unroll
        for (int ks = 0; ks < 4; ks++) {
            int kb = ks * 32;
            uint32_t ah[4], al[4];
            uint32_t oa = SWZ((uint32_t)(arow * 128 + kb + csel));
            ldm_x4(ah[0], ah[1], ah[2], ah[3], bA_h + oa);
            ldm_x4(al[0], al[1], al[2], al[3], bA_l + oa);

            uint32_t bh[9][2], bl[9][2];
#pragma unroll
            for (int p = 0; p < 4; p++) {
                uint32_t ob = SWZ((uint32_t)((n0w + p * 16 + (lane & 15)) * 128 + kb + csel));
                ldm_x4(bh[2 * p][0], bh[2 * p + 1][0], bh[2 * p][1], bh[2 * p + 1][1], bB_h + ob);
                ldm_x4(bl[2 * p][0], bl[2 * p + 1][0], bl[2 * p][1], bl[2 * p + 1][1], bB_l + ob);
            }
            {
                uint32_t ob = SWZ((uint32_t)((n0w + 64 + (lane & 7)) * 128 + kb +
                                             ((lane >> 3) & 1) * 16));
                ldm_x2(bh[8][0], bh[8][1], bB_h + ob);
                ldm_x2(bl[8][0], bl[8][1], bB_l + ob);
            }
#pragma unroll
            for (int nt = 0; nt < 9; nt++) {
                mma_bf16(acc[nt], ah, bh[nt]);
                mma_bf16(acc[nt], ah, bl[nt]);
                mma_bf16(acc[nt], al, bh[nt]);
            }
        }
        if (s + 1 < PRIM_NS) CP_WAIT0();
        __syncthreads();
    }

    // epilogue: /32 + bias, squash over 8 atoms (lanes xor 4,8,16), write x3.
    // warp rows: cap0 = rows 0-7 (j=0,1), cap1 = rows 8-15 (j=2,3); atom = lane>>2.
    int atom = lane >> 2;
    int cobase = co0 + warpM * 16;
    float bv0 = pb[cobase + atom];
    float bv1 = pb[cobase + 8 + atom];
    int cap0 = cobase >> 3;
#pragma unroll
    for (int nt = 0; nt < 9; nt++) {
        float pr0 = acc[nt][0] * (1.f / 32.f) + bv0;
        float pr1 = acc[nt][1] * (1.f / 32.f) + bv0;
        float pr2 = acc[nt][2] * (1.f / 32.f) + bv1;
        float pr3 = acc[nt][3] * (1.f / 32.f) + bv1;
        float s0 = pr0 * pr0, s1 = pr1 * pr1, s2 = pr2 * pr2, s3 = pr3 * pr3;
#pragma unroll
        for (int d = 4; d <= 16; d <<= 1) {
            s0 += __shfl_xor_sync(0xffffffffu, s0, d);
            s1 += __shfl_xor_sync(0xffffffffu, s1, d);
            s2 += __shfl_xor_sync(0xffffffffu, s2, d);
            s3 += __shfl_xor_sync(0xffffffffu, s3, d);
        }
        float c0 = (s0 / (1.f + s0)) * rsqrtf(s0 + 1e-9f);
        float c1 = (s1 / (1.f + s1)) * rsqrtf(s1 + 1e-9f);
        float c2 = (s2 / (1.f + s2)) * rsqrtf(s2 + 1e-9f);
        float c3 = (s3 / (1.f + s3)) * rsqrtf(s3 + 1e-9f);
        int ncol = n0w + nt * 8 + (lane & 3) * 2;
        int bb = b0 + ncol / 36, sp = ncol % 36;
        float* base = g_x3 + bb * 9216;
        base[(cap0 * 36 + sp) * 8 + atom] = pr0 * c0;
        base[(cap0 * 36 + sp + 1) * 8 + atom] = pr1 * c1;
        base[((cap0 + 1) * 36 + sp) * 8 + atom] = pr2 * c2;
        base[((cap0 + 1) * 36 + sp + 1) * 8 + atom] = pr3 * c3;
    }
}

// ---------------- K3: votes [i][b][ot], block per i, w reused across 256 b --------
__global__ __launch_bounds__(256) void k_votes(const float* __restrict__ dw) {
    int i = blockIdx.x, t = threadIdx.x;    // t = b
    __shared__ float ws[1280];
    __shared__ float stg[256 * 17];
    for (int e = t; e < 1280; e += 256) ws[e] = dw[i * 1280 + e];
    const float4* xp = (const float4*)(g_x3 + t * 9216 + i * 8);
    float4 a0 = xp[0], a1 = xp[1];
    float xv[8] = {a0.x, a0.y, a0.z, a0.w, a1.x, a1.y, a1.z, a1.w};
    unsigned long long xpk[8];
#pragma unroll
    for (int a = 0; a < 8; a++) xpk[a] = pk2(xv[a], xv[a]);
    __syncthreads();
    float* orow = g_votes + (long)i * 40960;
    for (int c = 0; c < 160; c += 16) {
        unsigned long long acc[8];
#pragma unroll
        for (int g = 0; g < 8; g++) acc[g] = 0ull;
#pragma unroll
        for (int a = 0; a < 8; a++) {
            const float2* wp = (const float2*)(ws + a * 160 + c);
#pragma unroll
            for (int g = 0; g < 8; g++) {
                float2 wv = wp[g];
                fma2(acc[g], xpk[a], pk2(wv.x, wv.y));
            }
        }
#pragma unroll
        for (int g = 0; g < 8; g++) {
            float2 f = upk2(acc[g]);
            stg[t * 17 + 2 * g] = f.x;
            stg[t * 17 + 2 * g + 1] = f.y;
        }
        __syncthreads();
        for (int e = t; e < 4096; e += 256) {
            int b = e >> 4, j = e & 15;
            orow[b * 160 + c + j] = stg[b * 17 + j];
        }
        __syncthreads();
    }
}

// ---------------- K4: fused 3-iteration routing -----------------------------------
__global__ __launch_bounds__(512) void k_route(const float* __restrict__ db,
                                               float* __restrict__ out_digit) {
    int b = blockIdx.x, t = threadIdx.x;
    int w = t >> 5, l = t & 31;
    __shared__ float act[160], asum[160], pre[160];
    __shared__ float red[16 * 160];
    const float* V = g_votes + b * 160;

    {
        float p0[5] = {0.f, 0.f, 0.f, 0.f, 0.f};
        for (int i = w; i < 1152; i += 16) {
            const float* vp = V + (long)i * 40960;
#pragma unroll
            for (int k = 0; k < 5; k++) p0[k] += vp[32 * k + l];
        }
#pragma unroll
        for (int k = 0; k < 5; k++) red[w * 160 + 32 * k + l] = p0[k];
    }
    __syncthreads();
    if (t < 160) {
        float s = 0.f;
#pragma unroll
        for (int ww = 0; ww < 16; ww++) s += red[ww * 160 + t];
        pre[t] = 0.1f * s + db[t];
    }
    __syncthreads();
    if (t < 160) {
        int o = t >> 4;
        float n2 = 0.f;
#pragma unroll
        for (int k = 0; k < 16; k++) { float v = pre[o * 16 + k]; n2 = fmaf(v, v, n2); }
        float a = pre[t] * (n2 / (1.f + n2)) * rsqrtf(n2 + 1e-9f);
        act[t] = a; asum[t] = a;
    }
    __syncthreads();

    for (int pass = 1; pass <= 2; pass++) {
        float pacc[5] = {0.f, 0.f, 0.f, 0.f, 0.f};
        for (int i = w; i < 1152; i += 16) {
            const float* vp = V + (long)i * 40960;
            float v[5], d[5];
#pragma unroll
            for (int k = 0; k < 5; k++) v[k] = vp[32 * k + l];
#pragma unroll
            for (int k = 0; k < 5; k++) {
                float s = v[k] * asum[32 * k + l];
                s += __shfl_xor_sync(0xffffffffu, s, 1);
                s += __shfl_xor_sync(0xffffffffu, s, 2);
                s += __shfl_xor_sync(0xffffffffu, s, 4);
                s += __shfl_xor_sync(0xffffffffu, s, 8);
                d[k] = s;
            }
            float dn[5];
#pragma unroll
            for (int k = 0; k < 5; k++) dn[k] = __shfl_xor_sync(0xffffffffu, d[k], 16);
            float m = -1e30f;
#pragma unroll
            for (int k = 0; k < 5; k++) m = fmaxf(m, fmaxf(d[k], dn[k]));
            float sum = 0.f, e[5];
#pragma unroll
            for (int k = 0; k < 5; k++) {
                e[k] = __expf(d[k] - m); sum += e[k];
                sum += __expf(dn[k] - m);
            }
            float inv = 1.f / sum;
#pragma unroll
            for (int k = 0; k < 5; k++) pacc[k] = fmaf(e[k] * inv, v[k], pacc[k]);
        }
#pragma unroll
        for (int k = 0; k < 5; k++) red[w * 160 + 32 * k + l] = pacc[k];
        __syncthreads();
        if (t < 160) {
            float s = 0.f;
#pragma unroll
            for (int ww = 0; ww < 16; ww++) s += red[ww * 160 + t];
            pre[t] = s + db[t];
        }
        __syncthreads();
        if (t < 160) {
            int o = t >> 4;
            float n2 = 0.f;
#pragma unroll
            for (int k = 0; k < 16; k++) { float v = pre[o * 16 + k]; n2 = fmaf(v, v, n2); }
            float a = pre[t] * (n2 / (1.f + n2)) * rsqrtf(n2 + 1e-9f);
            act[t] = a;
            if (pass == 1) asum[t] += a;
        }
        __syncthreads();
    }
    if (t < 160) out_digit[b * 160 + t] = act[t];
}

// ---------------- K5: reconstruction MLP ------------------------------------------
__global__ __launch_bounds__(512) void k_fc1(const float* __restrict__ w1,
                                             const float* __restrict__ b1,
                                             const float* __restrict__ y,
                                             const float* __restrict__ digit) {
    int b = blockIdx.x, t = threadIdx.x;
    __shared__ float m[160];
    if (t < 160) m[t] = digit[b * 160 + t] * y[b * 10 + (t >> 4)];
    __syncthreads();
    float acc = b1[t];
#pragma unroll 8
    for (int k = 0; k < 160; k++) acc = fmaf(m[k], w1[k * 512 + t], acc);
    g_r1[b * 512 + t] = fmaxf(acc, 0.f);
}

__global__ __launch_bounds__(1024) void k_fc2(const float* __restrict__ w2,
                                              const float* __restrict__ b2) {
    int b0 = blockIdx.x * 2, t = threadIdx.x;
    __shared__ float m[2][512];
    if (t < 512) m[0][t] = g_r1[b0 * 512 + t];
    else m[1][t - 512] = g_r1[(b0 + 1) * 512 + t - 512];
    __syncthreads();
    float a0 = b2[t], a1 = a0;
#pragma unroll 8
    for (int k = 0; k < 512; k++) {
        float wv = w2[k * 1024 + t];
        a0 = fmaf(m[0][k], wv, a0);
        a1 = fmaf(m[1][k], wv, a1);
    }
    g_r2[b0 * 1024 + t] = fmaxf(a0, 0.f);
    g_r2[(b0 + 1) * 1024 + t] = fmaxf(a1, 0.f);
}

__global__ __launch_bounds__(784) void k_fc3(const float* __restrict__ w3,
                                             const float* __restrict__ b3,
                                             float* __restrict__ recon) {
    int b0 = blockIdx.x * 2, t = threadIdx.x;
    __shared__ float m[2][1024];
    for (int e = t; e < 2048; e += 784) {
        int bb = e >> 10;
        m[bb][e & 1023] = g_r2[(b0 + bb) * 1024 + (e & 1023)];
    }
    __syncthreads();
    float a0 = b3[t], a1 = a0;
#pragma unroll 8
    for (int k = 0; k < 1024; k++) {
        float wv = w3[k * 784 + t];
        a0 = fmaf(m[0][k], wv, a0);
        a1 = fmaf(m[1][k], wv, a1);
    }
    recon[b0 * 784 + t] = 1.f / (1.f + __expf(-a0));
    recon[(b0 + 1) * 784 + t] = 1.f / (1.f + __expf(-a1));
}

// ---------------- launch -----------------------------------------------------------
extern "C" void kernel_launch(void* const* d_in, const int* in_sizes, int n_in,
                              void* d_out, int out_size) {
    const float* x   = (const float*)d_in[0];
    const float* y   = (const float*)d_in[1];
    const float* c1w = (const float*)d_in[2];
    const float* c1b = (const float*)d_in[3];
    const float* pw  = (const float*)d_in[4];
    const float* pb  = (const float*)d_in[5];
    const float* dw  = (const float*)d_in[6];
    const float* db  = (const float*)d_in[7];
    const float* w1  = (const float*)d_in[8];
    const float* b1  = (const float*)d_in[9];
    const float* w2  = (const float*)d_in[10];
    const float* b2  = (const float*)d_in[11];
    const float* w3  = (const float*)d_in[12];
    const float* b3  = (const float*)d_in[13];
    float* out = (float*)d_out;   // digit [0,40960), recon [40960,241664)

    cudaFuncSetAttribute(k_prim, cudaFuncAttributeMaxDynamicSharedMemorySize, 139264);

    k_wsplit<<<10368, 512>>>(pw);
    k_conv1<<<dim3(8, 256), 400>>>(x, c1w, c1b);
    k_prim<<<dim3(2, 64), 512, 139264>>>(pb);
    k_votes<<<1152, 256>>>(dw);
    k_route<<<256, 512>>>(db, out);
    k_fc1<<<256, 512>>>(w1, b1, y, out);
    k_fc2<<<128, 1024>>>(w2, b2);
    k_fc3<<<128, 784>>>(w3, b3, out + 40960);
}

// round 10
// speedup vs baseline: 1.8781x; 1.8781x over previous
#include <cuda_runtime.h>
#include <cuda_fp16.h>
#include <math.h>
#include <stdint.h>

// ---------------- scratch (device globals) ---------------------------------------
__device__ __half g_hh[26214400];          // conv1 out fp16, [b][pos400][ci256]
__device__ __half g_whi[5308416];          // prim weights hi fp16, [tap81][co256][ci256]
__device__ __half g_wlo[5308416];          // prim weights lo fp16
__device__ float g_x3[256 * 1152 * 8];     // squashed primary caps [b][i][a]
__device__ float g_votes[47185920];        // votes [i][b][ot]
__device__ float g_r1[256 * 512];
__device__ float g_r2[256 * 1024];

// ---------------- f32x2 helpers ---------------------------------------------------
__device__ __forceinline__ unsigned long long pk2(float lo, float hi) {
    unsigned long long r;
    asm("mov.b64 %0, {%1, %2};" : "=l"(r) : "f"(lo), "f"(hi));
    return r;
}
__device__ __forceinline__ void fma2(unsigned long long& d, unsigned long long a,
                                     unsigned long long b) {
    asm("fma.rn.f32x2 %0, %1, %2, %0;" : "+l"(d) : "l"(a), "l"(b));
}
__device__ __forceinline__ float2 upk2(unsigned long long v) {
    float2 f;
    asm("mov.b64 {%0, %1}, %2;" : "=f"(f.x), "=f"(f.y) : "l"(v));
    return f;
}

// ---------------- baseline-PTX helpers --------------------------------------------
__device__ __forceinline__ uint32_t smem_to_u32(const void* p) {
    uint32_t a;
    asm("{ .reg .u64 t; cvta.to.shared.u64 t, %1; cvt.u32.u64 %0, t; }" : "=r"(a) : "l"(p));
    return a;
}
__device__ __forceinline__ void cpa16(uint32_t s, const void* g) {
    asm volatile("cp.async.cg.shared.global [%0], [%1], 16;" :: "r"(s), "l"(g));
}
#define CP_COMMIT() asm volatile("cp.async.commit_group;" ::: "memory")
#define CP_WAIT0()  asm volatile("cp.async.wait_group 0;" ::: "memory")

__device__ __forceinline__ void ldm_x4(uint32_t& r0, uint32_t& r1, uint32_t& r2,
                                       uint32_t& r3, uint32_t a) {
    asm volatile("ldmatrix.sync.aligned.m8n8.x4.shared.b16 {%0,%1,%2,%3}, [%4];"
                 : "=r"(r0), "=r"(r1), "=r"(r2), "=r"(r3) : "r"(a));
}
__device__ __forceinline__ void ldm_x2(uint32_t& r0, uint32_t& r1, uint32_t a) {
    asm volatile("ldmatrix.sync.aligned.m8n8.x2.shared.b16 {%0,%1}, [%2];"
                 : "=r"(r0), "=r"(r1) : "r"(a));
}
__device__ __forceinline__ void mma_f16(float* c, const uint32_t* a, const uint32_t* b) {
    asm volatile("mma.sync.aligned.m16n8k16.row.col.f32.f16.f16.f32 "
                 "{%0,%1,%2,%3}, {%4,%5,%6,%7}, {%8,%9}, {%0,%1,%2,%3};"
                 : "+f"(c[0]), "+f"(c[1]), "+f"(c[2]), "+f"(c[3])
                 : "r"(a[0]), "r"(a[1]), "r"(a[2]), "r"(a[3]), "r"(b[0]), "r"(b[1]));
}
#define SWZ(x) ((x) ^ (((x) >> 3) & 0x70))

// ---------------- P0: weight split/transpose, coalesced ---------------------------
// grid 256 (one co), 256 threads (ci). smem transpose to [tap][ci].
__global__ __launch_bounds__(256) void k_wsplit(const float* __restrict__ pw) {
    extern __shared__ unsigned sbuf[];   // 81*256
    int co = blockIdx.x, ci = threadIdx.x;
    const float* src = pw + co * 20736 + ci * 81;
#pragma unroll
    for (int tap = 0; tap < 81; tap++) {
        float w = src[tap];
        __half h = __float2half(w);
        __half l = __float2half(w - __half2float(h));
        sbuf[tap * 256 + ci] = (unsigned)__half_as_ushort(h) |
                               ((unsigned)__half_as_ushort(l) << 16);
    }
    __syncthreads();
    for (int e = ci; e < 81 * 256; e += 256) {
        int tap = e >> 8, c2 = e & 255;
        unsigned v = sbuf[e];
        g_whi[tap * 65536 + co * 256 + c2] = __ushort_as_half((unsigned short)(v & 0xffff));
        g_wlo[tap * 65536 + co * 256 + c2] = __ushort_as_half((unsigned short)(v >> 16));
    }
}

// ---------------- K1: conv1 9x9 s1 + bias + relu -> fp16 [b][pos][ci] -------------
__global__ __launch_bounds__(400) void k_conv1(const float* __restrict__ x,
                                               const float* __restrict__ w,
                                               const float* __restrict__ bias) {
    int b = blockIdx.y, c0 = blockIdx.x * 32;
    __shared__ float img[784];
    __shared__ float ws[32 * 81];
    __shared__ float bs[32];
    __shared__ unsigned short spk[100 * 32];
    int t = threadIdx.x;
    for (int e = t; e < 784; e += 400) img[e] = x[b * 784 + e];
    for (int e = t; e < 2592; e += 400) ws[e] = w[c0 * 81 + e];
    if (t < 32) bs[t] = bias[c0 + t];
    __syncthreads();

    int pg = t % 100, chg = t / 100;
    int p0 = pg * 4;
    int oy = p0 / 20, ox0 = p0 % 20;

    unsigned long long acc2[4][4];
#pragma unroll
    for (int p = 0; p < 4; p++)
#pragma unroll
        for (int j = 0; j < 4; j++) acc2[p][j] = 0ull;

    for (int kh = 0; kh < 9; kh++) {
        const float* row = img + (oy + kh) * 28 + ox0;
        float xw[12];
#pragma unroll
        for (int i = 0; i < 12; i++) xw[i] = row[i];
#pragma unroll
        for (int kw = 0; kw < 9; kw++) {
            unsigned long long xp[4];
#pragma unroll
            for (int j = 0; j < 4; j++) xp[j] = pk2(xw[kw + j], xw[kw + j]);
#pragma unroll
            for (int p = 0; p < 4; p++) {
                unsigned long long wp = pk2(ws[(chg * 8 + 2 * p) * 81 + kh * 9 + kw],
                                            ws[(chg * 8 + 2 * p + 1) * 81 + kh * 9 + kw]);
#pragma unroll
                for (int j = 0; j < 4; j++) fma2(acc2[p][j], xp[j], wp);
            }
        }
    }

    unsigned short pkv[8][4];
#pragma unroll
    for (int p = 0; p < 4; p++) {
        float b0v = bs[chg * 8 + 2 * p], b1v = bs[chg * 8 + 2 * p + 1];
#pragma unroll
        for (int j = 0; j < 4; j++) {
            float2 f = upk2(acc2[p][j]);
            pkv[2 * p][j] = __half_as_ushort(__float2half(fmaxf(f.x + b0v, 0.f)));
            pkv[2 * p + 1][j] = __half_as_ushort(__float2half(fmaxf(f.y + b1v, 0.f)));
        }
    }
    for (int c = 0; c < 4; c++) {
        if (pg >= c * 25 && pg < c * 25 + 25) {
            int pl = p0 - c * 100;
#pragma unroll
            for (int ch = 0; ch < 8; ch++)
#pragma unroll
                for (int j = 0; j < 4; j++)
                    spk[(pl + j) * 32 + chg * 8 + ch] = pkv[ch][j];
        }
        __syncthreads();
        for (int e = t; e < 3200; e += 400) {
            int pl = e >> 5, ch = e & 31;
            g_hh[(b * 400 + c * 100 + pl) * 256 + c0 + ch] = __ushort_as_half(spk[e]);
        }
        __syncthreads();
    }
}

// ---------------- K2: primary-caps conv, fp16 2-term split, ks-pipelined ----------
// grid (2 co-halves of 128, 64 b-groups of 4), 256 thr = 8 warps (4M x 2N).
// CTA tile: M=128 co, N=144 (4b x 36 pos), K = 81 taps x 4 ci-blocks(64) = 324 stages.
static constexpr int PRIM_NS = 324;

__global__ __launch_bounds__(256, 1) void k_prim(const float* __restrict__ pb) {
    extern __shared__ char sm[];
    uint32_t sb = smem_to_u32(sm);
    const int t = threadIdx.x, wid = t >> 5, lane = t & 31;
    const int co0 = blockIdx.x * 128;
    const int b0 = blockIdx.y * 4;
    const int warpM = wid >> 1, warpN = wid & 1;

    // buffers (16KB A-hi, 16KB A-lo, 18KB B) packed exactly into 102400 bytes:
    // buf0: AH 0, AL 16384, BH 32768..51200
    // buf1: AH 51200, AL 67584, BH 83968..102400
    const uint32_t AH[2] = {0u, 51200u};
    const uint32_t AL[2] = {16384u, 67584u};
    const uint32_t BH[2] = {32768u, 83968u};

    uint32_t a_sm[4]; long a_g[4];
#pragma unroll
    for (int k = 0; k < 4; k++) {
        int e = t + k * 256, row = e >> 3, q = e & 7;
        a_sm[k] = SWZ((uint32_t)(row * 128 + q * 16));
        a_g[k] = (long)(co0 + row) * 256 + q * 8;
    }
    uint32_t b_sm[5]; long b_g[5]; bool b_p[5];
#pragma unroll
    for (int k = 0; k < 5; k++) {
        int e = t + k * 256;
        b_p[k] = (e < 1152);
        int n = e >> 3, q = e & 7;
        if (!b_p[k]) { n = 0; q = 0; }
        int bb = n / 36, sp = n % 36, oy = sp / 6, ox = sp % 6;
        b_sm[k] = SWZ((uint32_t)(n * 128 + q * 16));
        b_g[k] = (long)((b0 + bb) * 400 + oy * 40 + ox * 2) * 256 + q * 8;
    }

    auto stage = [&](int buf, int s) {
        int tap = s >> 2, cb = s & 3;
        long wofs = (long)tap * 65536 + cb * 64;
        long xofs = (long)((tap / 9) * 20 + (tap % 9)) * 256 + cb * 64;
#pragma unroll
        for (int k = 0; k < 4; k++) {
            cpa16(sb + AH[buf] + a_sm[k], g_whi + wofs + a_g[k]);
            cpa16(sb + AL[buf] + a_sm[k], g_wlo + wofs + a_g[k]);
        }
#pragma unroll
        for (int k = 0; k < 5; k++)
            if (b_p[k]) cpa16(sb + BH[buf] + b_sm[k], g_hh + xofs + b_g[k]);
        CP_COMMIT();
    };

    float acc[2][9][4];
#pragma unroll
    for (int mt = 0; mt < 2; mt++)
#pragma unroll
        for (int nt = 0; nt < 9; nt++)
#pragma unroll
            for (int j = 0; j < 4; j++) acc[mt][nt][j] = 0.f;

    const int arow = warpM * 32 + (lane & 15);
    const int n0w = warpN * 72;
    const int csel = (lane >> 4) * 16;

    // fragment double-buffer (fb = ks&1)
    uint32_t ahf[2][2][4], alf[2][2][4], bhf[2][9][2];

    stage(0, 0);
    CP_WAIT0();
    __syncthreads();

    for (int s = 0; s < PRIM_NS; s++) {
        int cur = s & 1;
        if (s + 1 < PRIM_NS) stage(cur ^ 1, s + 1);

        uint32_t bA_h = sb + AH[cur], bA_l = sb + AL[cur], bB_h = sb + BH[cur];

#define LOADFRAG(PB, KS) do { \
        int kb_ = (KS) * 32; \
        uint32_t oa0_ = SWZ((uint32_t)(arow * 128 + kb_ + csel)); \
        uint32_t oa1_ = SWZ((uint32_t)((arow + 16) * 128 + kb_ + csel)); \
        ldm_x4(ahf[PB][0][0], ahf[PB][0][1], ahf[PB][0][2], ahf[PB][0][3], bA_h + oa0_); \
        ldm_x4(ahf[PB][1][0], ahf[PB][1][1], ahf[PB][1][2], ahf[PB][1][3], bA_h + oa1_); \
        ldm_x4(alf[PB][0][0], alf[PB][0][1], alf[PB][0][2], alf[PB][0][3], bA_l + oa0_); \
        ldm_x4(alf[PB][1][0], alf[PB][1][1], alf[PB][1][2], alf[PB][1][3], bA_l + oa1_); \
        _Pragma("unroll") \
        for (int p_ = 0; p_ < 4; p_++) { \
            uint32_t ob_ = SWZ((uint32_t)((n0w + p_ * 16 + (lane & 15)) * 128 + kb_ + csel)); \
            ldm_x4(bhf[PB][2 * p_][0], bhf[PB][2 * p_ + 1][0], \
                   bhf[PB][2 * p_][1], bhf[PB][2 * p_ + 1][1], bB_h + ob_); \
        } \
        { uint32_t ob2_ = SWZ((uint32_t)((n0w + 64 + (lane & 7)) * 128 + kb_ + \
                                         ((lane >> 3) & 1) * 16)); \
          ldm_x2(bhf[PB][8][0], bhf[PB][8][1], bB_h + ob2_); } \
    } while (0)

        LOADFRAG(0, 0);
#pragma unroll
        for (int ks = 0; ks < 4; ks++) {
            if (ks == 0) LOADFRAG(1, 1);
            else if (ks == 1) LOADFRAG(0, 2);
            else if (ks == 2) LOADFRAG(1, 3);
            const int fb = ks & 1;
#pragma unroll
            for (int mt = 0; mt < 2; mt++)
#pragma unroll
                for (int nt = 0; nt < 9; nt++) {
                    mma_f16(acc[mt][nt], ahf[fb][mt], bhf[fb][nt]);
                    mma_f16(acc[mt][nt], alf[fb][mt], bhf[fb][nt]);
                }
        }
#undef LOADFRAG
        if (s + 1 < PRIM_NS) CP_WAIT0();
        __syncthreads();
    }

    // epilogue: /32 + bias, squash over 8 atoms (lanes xor 4,8,16), write x3
    int atom = lane >> 2;
#pragma unroll
    for (int mt = 0; mt < 2; mt++) {
        int cobase = co0 + warpM * 32 + mt * 16;
        float bv0 = pb[cobase + atom];
        float bv1 = pb[cobase + 8 + atom];
        int cap0 = (cobase >> 3);
#pragma unroll
        for (int nt = 0; nt < 9; nt++) {
            float pr0 = acc[mt][nt][0] * (1.f / 32.f) + bv0;
            float pr1 = acc[mt][nt][1] * (1.f / 32.f) + bv0;
            float pr2 = acc[mt][nt][2] * (1.f / 32.f) + bv1;
            float pr3 = acc[mt][nt][3] * (1.f / 32.f) + bv1;
            float s0 = pr0 * pr0, s1 = pr1 * pr1, s2 = pr2 * pr2, s3 = pr3 * pr3;
#pragma unroll
            for (int d = 4; d <= 16; d <<= 1) {
                s0 += __shfl_xor_sync(0xffffffffu, s0, d);
                s1 += __shfl_xor_sync(0xffffffffu, s1, d);
                s2 += __shfl_xor_sync(0xffffffffu, s2, d);
                s3 += __shfl_xor_sync(0xffffffffu, s3, d);
            }
            float c0 = (s0 / (1.f + s0)) * rsqrtf(s0 + 1e-9f);
            float c1 = (s1 / (1.f + s1)) * rsqrtf(s1 + 1e-9f);
            float c2 = (s2 / (1.f + s2)) * rsqrtf(s2 + 1e-9f);
            float c3 = (s3 / (1.f + s3)) * rsqrtf(s3 + 1e-9f);
            int ncol = n0w + nt * 8 + (lane & 3) * 2;
            int bb = b0 + ncol / 36, sp = ncol % 36;
            float* base = g_x3 + bb * 9216;
            base[(cap0 * 36 + sp) * 8 + atom] = pr0 * c0;
            base[(cap0 * 36 + sp + 1) * 8 + atom] = pr1 * c1;
            base[((cap0 + 1) * 36 + sp) * 8 + atom] = pr2 * c2;
            base[((cap0 + 1) * 36 + sp + 1) * 8 + atom] = pr3 * c3;
        }
    }
}

// ---------------- K3: votes [i][b][ot], block per i --------------------------------
__global__ __launch_bounds__(256) void k_votes(const float* __restrict__ dw) {
    int i = blockIdx.x, t = threadIdx.x;    // t = b
    __shared__ float ws[1280];
    __shared__ float stg[256 * 17];
    for (int e = t; e < 1280; e += 256) ws[e] = dw[i * 1280 + e];
    const float4* xp = (const float4*)(g_x3 + t * 9216 + i * 8);
    float4 a0 = xp[0], a1 = xp[1];
    float xv[8] = {a0.x, a0.y, a0.z, a0.w, a1.x, a1.y, a1.z, a1.w};
    unsigned long long xpk[8];
#pragma unroll
    for (int a = 0; a < 8; a++) xpk[a] = pk2(xv[a], xv[a]);
    __syncthreads();
    float* orow = g_votes + (long)i * 40960;
    for (int c = 0; c < 160; c += 16) {
        unsigned long long acc[8];
#pragma unroll
        for (int g = 0; g < 8; g++) acc[g] = 0ull;
#pragma unroll
        for (int a = 0; a < 8; a++) {
            const float2* wp = (const float2*)(ws + a * 160 + c);
#pragma unroll
            for (int g = 0; g < 8; g++) {
                float2 wv = wp[g];
                fma2(acc[g], xpk[a], pk2(wv.x, wv.y));
            }
        }
#pragma unroll
        for (int g = 0; g < 8; g++) {
            float2 f = upk2(acc[g]);
            stg[t * 17 + 2 * g] = f.x;
            stg[t * 17 + 2 * g + 1] = f.y;
        }
        __syncthreads();
        for (int e = t; e < 4096; e += 256) {
            int b = e >> 4, j = e & 15;
            orow[b * 160 + c + j] = stg[b * 17 + j];
        }
        __syncthreads();
    }
}

// ---------------- K4: fused 3-iteration routing ------------------------------------
__global__ __launch_bounds__(512) void k_route(const float* __restrict__ db,
                                               float* __restrict__ out_digit) {
    int b = blockIdx.x, t = threadIdx.x;
    int w = t >> 5, l = t & 31;
    __shared__ float act[160], asum[160], pre[160];
    __shared__ float red[16 * 160];
    const float* V = g_votes + b * 160;

    {
        float p0[5] = {0.f, 0.f, 0.f, 0.f, 0.f};
        for (int i = w; i < 1152; i += 16) {
            const float* vp = V + (long)i * 40960;
#pragma unroll
            for (int k = 0; k < 5; k++) p0[k] += vp[32 * k + l];
        }
#pragma unroll
        for (int k = 0; k < 5; k++) red[w * 160 + 32 * k + l] = p0[k];
    }
    __syncthreads();
    if (t < 160) {
        float s = 0.f;
#pragma unroll
        for (int ww = 0; ww < 16; ww++) s += red[ww * 160 + t];
        pre[t] = 0.1f * s + db[t];
    }
    __syncthreads();
    if (t < 160) {
        int o = t >> 4;
        float n2 = 0.f;
#pragma unroll
        for (int k = 0; k < 16; k++) { float v = pre[o * 16 + k]; n2 = fmaf(v, v, n2); }
        float a = pre[t] * (n2 / (1.f + n2)) * rsqrtf(n2 + 1e-9f);
        act[t] = a; asum[t] = a;
    }
    __syncthreads();

    for (int pass = 1; pass <= 2; pass++) {
        float pacc[5] = {0.f, 0.f, 0.f, 0.f, 0.f};
        for (int i = w; i < 1152; i += 16) {
            const float* vp = V + (long)i * 40960;
            float v[5], d[5];
#pragma unroll
            for (int k = 0; k < 5; k++) v[k] = vp[32 * k + l];
#pragma unroll
            for (int k = 0; k < 5; k++) {
                float s = v[k] * asum[32 * k + l];
                s += __shfl_xor_sync(0xffffffffu, s, 1);
                s += __shfl_xor_sync(0xffffffffu, s, 2);
                s += __shfl_xor_sync(0xffffffffu, s, 4);
                s += __shfl_xor_sync(0xffffffffu, s, 8);
                d[k] = s;
            }
            float dn[5];
#pragma unroll
            for (int k = 0; k < 5; k++) dn[k] = __shfl_xor_sync(0xffffffffu, d[k], 16);
            float m = -1e30f;
#pragma unroll
            for (int k = 0; k < 5; k++) m = fmaxf(m, fmaxf(d[k], dn[k]));
            float sum = 0.f, e[5];
#pragma unroll
            for (int k = 0; k < 5; k++) {
                e[k] = __expf(d[k] - m); sum += e[k];
                sum += __expf(dn[k] - m);
            }
            float inv = 1.f / sum;
#pragma unroll
            for (int k = 0; k < 5; k++) pacc[k] = fmaf(e[k] * inv, v[k], pacc[k]);
        }
#pragma unroll
        for (int k = 0; k < 5; k++) red[w * 160 + 32 * k + l] = pacc[k];
        __syncthreads();
        if (t < 160) {
            float s = 0.f;
#pragma unroll
            for (int ww = 0; ww < 16; ww++) s += red[ww * 160 + t];
            pre[t] = s + db[t];
        }
        __syncthreads();
        if (t < 160) {
            int o = t >> 4;
            float n2 = 0.f;
#pragma unroll
            for (int k = 0; k < 16; k++) { float v = pre[o * 16 + k]; n2 = fmaf(v, v, n2); }
            float a = pre[t] * (n2 / (1.f + n2)) * rsqrtf(n2 + 1e-9f);
            act[t] = a;
            if (pass == 1) asum[t] += a;
        }
        __syncthreads();
    }
    if (t < 160) out_digit[b * 160 + t] = act[t];
}

// ---------------- K5: reconstruction MLP -------------------------------------------
__global__ __launch_bounds__(512) void k_fc1(const float* __restrict__ w1,
                                             const float* __restrict__ b1,
                                             const float* __restrict__ y,
                                             const float* __restrict__ digit) {
    int b = blockIdx.x, t = threadIdx.x;
    __shared__ float m[160];
    if (t < 160) m[t] = digit[b * 160 + t] * y[b * 10 + (t >> 4)];
    __syncthreads();
    float acc = b1[t];
#pragma unroll 8
    for (int k = 0; k < 160; k++) acc = fmaf(m[k], w1[k * 512 + t], acc);
    g_r1[b * 512 + t] = fmaxf(acc, 0.f);
}

__global__ __launch_bounds__(1024) void k_fc2(const float* __restrict__ w2,
                                              const float* __restrict__ b2) {
    int b0 = blockIdx.x * 2, t = threadIdx.x;
    __shared__ float m[2][512];
    if (t < 512) m[0][t] = g_r1[b0 * 512 + t];
    else m[1][t - 512] = g_r1[(b0 + 1) * 512 + t - 512];
    __syncthreads();
    float a0 = b2[t], a1 = a0;
#pragma unroll 8
    for (int k = 0; k < 512; k++) {
        float wv = w2[k * 1024 + t];
        a0 = fmaf(m[0][k], wv, a0);
        a1 = fmaf(m[1][k], wv, a1);
    }
    g_r2[b0 * 1024 + t] = fmaxf(a0, 0.f);
    g_r2[(b0 + 1) * 1024 + t] = fmaxf(a1, 0.f);
}

__global__ __launch_bounds__(784) void k_fc3(const float* __restrict__ w3,
                                             const float* __restrict__ b3,
                                             float* __restrict__ recon) {
    int b0 = blockIdx.x * 2, t = threadIdx.x;
    __shared__ float m[2][1024];
    for (int e = t; e < 2048; e += 784) {
        int bb = e >> 10;
        m[bb][e & 1023] = g_r2[(b0 + bb) * 1024 + (e & 1023)];
    }
    __syncthreads();
    float a0 = b3[t], a1 = a0;
#pragma unroll 8
    for (int k = 0; k < 1024; k++) {
        float wv = w3[k * 784 + t];
        a0 = fmaf(m[0][k], wv, a0);
        a1 = fmaf(m[1][k], wv, a1);
    }
    recon[b0 * 784 + t] = 1.f / (1.f + __expf(-a0));
    recon[(b0 + 1) * 784 + t] = 1.f / (1.f + __expf(-a1));
}

// ---------------- launch ------------------------------------------------------------
extern "C" void kernel_launch(void* const* d_in, const int* in_sizes, int n_in,
                              void* d_out, int out_size) {
    const float* x   = (const float*)d_in[0];
    const float* y   = (const float*)d_in[1];
    const float* c1w = (const float*)d_in[2];
    const float* c1b = (const float*)d_in[3];
    const float* pw  = (const float*)d_in[4];
    const float* pb  = (const float*)d_in[5];
    const float* dw  = (const float*)d_in[6];
    const float* db  = (const float*)d_in[7];
    const float* w1  = (const float*)d_in[8];
    const float* b1  = (const float*)d_in[9];
    const float* w2  = (const float*)d_in[10];
    const float* b2  = (const float*)d_in[11];
    const float* w3  = (const float*)d_in[12];
    const float* b3  = (const float*)d_in[13];
    float* out = (float*)d_out;   // digit [0,40960), recon [40960,241664)

    cudaFuncSetAttribute(k_prim, cudaFuncAttributeMaxDynamicSharedMemorySize, 102400);
    cudaFuncSetAttribute(k_wsplit, cudaFuncAttributeMaxDynamicSharedMemorySize, 82944);

    k_wsplit<<<256, 256, 82944>>>(pw);
    k_conv1<<<dim3(8, 256), 400>>>(x, c1w, c1b);
    k_prim<<<dim3(2, 64), 256, 102400>>>(pb);
    k_votes<<<1152, 256>>>(dw);
    k_route<<<256, 512>>>(db, out);
    k_fc1<<<256, 512>>>(w1, b1, y, out);
    k_fc2<<<128, 1024>>>(w2, b2);
    k_fc3<<<128, 784>>>(w3, b3, out + 40960);
}